// round 16
// baseline (speedup 1.0000x reference)
#include <cuda_runtime.h>
#include <cuda_fp16.h>
#include <cstdint>

// ---------------- problem constants ----------------
#define N_SPK 8192
#define M_UTT 10
#define D_EMB 128
#define CLAMP_MIN 1e-6f

// ---------------- gemm tiling ----------------
#define TM 128
#define TN 256
#define NCT 32                         // col tiles per row block
#define NRB 64                         // row blocks
#define TOTAL_TILES (NRB * NCT)        // 2048
#define NCTA 148                       // one CTA per SM, one wave
#define GTHREADS 256                   // 8 warps: 2(M) x 4(N), warp tile 64x64

#define ROW_BYTES 256                  // 128 fp16
#define A_BYTES (128 * ROW_BYTES)      // 32 KB
#define B_BYTES (256 * ROW_BYTES)      // 64 KB
#define OFF_B0  (2 * A_BYTES)          // A double buffer at 0 / 32KB
#define OFF_RED (2 * A_BYTES + 2 * B_BYTES)
#define SMEM_TOTAL (OFF_RED + 2048)    // 194 KB + 2KB reduction pad

// ---------------- device scratch ----------------
__device__ __align__(16) __half g_lhat[N_SPK * D_EMB];
__device__ __align__(16) __half g_chat[N_SPK * D_EMB];
// Sparse per-segment exp-sum partials (slot = segment-start ct); unwritten
// slots stay zero, each written slot has exactly one writer per launch.
__device__ float g_partF[NCT][N_SPK];
__device__ float g_diag[N_SPK];
__device__ float g_blk[NRB];
__device__ unsigned int g_cnt;

// ---------------- helpers ----------------
__device__ __forceinline__ uint32_t smem_u32(const void* p) {
    uint32_t a;
    asm("{ .reg .u64 t; cvta.to.shared.u64 t, %1; cvt.u32.u64 %0, t; }" : "=r"(a) : "l"(p));
    return a;
}
__device__ __forceinline__ void cp16(uint32_t dst, const void* src) {
    asm volatile("cp.async.cg.shared.global [%0], [%1], 16;" :: "r"(dst), "l"(src) : "memory");
}
#define CP_COMMIT() asm volatile("cp.async.commit_group;" ::: "memory")
#define CP_WAIT0()  asm volatile("cp.async.wait_group 0;" ::: "memory")

#define LDMX4(r0, r1, r2, r3, addr)                                            \
    asm volatile("ldmatrix.sync.aligned.m8n8.x4.shared.b16 {%0,%1,%2,%3}, [%4];" \
                 : "=r"(r0), "=r"(r1), "=r"(r2), "=r"(r3) : "r"(addr))

// fp16-accumulate HMMA: D,C in f16x2 pairs (2 regs), A/B f16.
__device__ __forceinline__ void mma_f16acc(uint32_t& c0, uint32_t& c1,
                                           uint32_t a0, uint32_t a1,
                                           uint32_t a2, uint32_t a3,
                                           uint32_t b0, uint32_t b1) {
    asm volatile(
        "mma.sync.aligned.m16n8k16.row.col.f16.f16.f16.f16 "
        "{%0,%1}, {%2,%3,%4,%5}, {%6,%7}, {%0,%1};"
        : "+r"(c0), "+r"(c1)
        : "r"(a0), "r"(a1), "r"(a2), "r"(a3), "r"(b0), "r"(b1));
}

__device__ __forceinline__ float ex2f(float x) {
    float r; asm("ex2.approx.ftz.f32 %0, %1;" : "=f"(r) : "f"(x)); return r;
}
__device__ __forceinline__ float lg2f(float x) {
    float r; asm("lg2.approx.f32 %0, %1;" : "=f"(r) : "f"(x)); return r;
}

// ---------------------------------------------------------------------------
// Kernel 1: centroids + normalization + fp16 rounding. (DRAM-bound, ~10.5us)
// ---------------------------------------------------------------------------
__global__ void __launch_bounds__(256) prep_kernel(const float* __restrict__ x) {
    if (blockIdx.x == 0 && threadIdx.x == 0) g_cnt = 0;

    const int lane = threadIdx.x & 31;
    const int n = blockIdx.x * 8 + (threadIdx.x >> 5);
    const float4* xs = (const float4*)(x + (size_t)n * (M_UTT * D_EMB));

    float4 c = make_float4(0.f, 0.f, 0.f, 0.f);
    float4 l;
#pragma unroll
    for (int m = 0; m < M_UTT; m++) {
        float4 v = xs[m * 32 + lane];
        c.x += v.x; c.y += v.y; c.z += v.z; c.w += v.w;
        if (m == M_UTT - 1) l = v;
    }
    c.x *= 0.1f; c.y *= 0.1f; c.z *= 0.1f; c.w *= 0.1f;

    float sc = c.x * c.x + c.y * c.y + c.z * c.z + c.w * c.w;
    float sl = l.x * l.x + l.y * l.y + l.z * l.z + l.w * l.w;
#pragma unroll
    for (int o = 16; o; o >>= 1) {
        sc += __shfl_xor_sync(0xffffffffu, sc, o);
        sl += __shfl_xor_sync(0xffffffffu, sl, o);
    }
    const float rc = rsqrtf(sc), rl = rsqrtf(sl);

    __half2 c01 = __floats2half2_rn(c.x * rc, c.y * rc);
    __half2 c23 = __floats2half2_rn(c.z * rc, c.w * rc);
    __half2 l01 = __floats2half2_rn(l.x * rl, l.y * rl);
    __half2 l23 = __floats2half2_rn(l.z * rl, l.w * rl);

    uint2 cv, lv;
    cv.x = *(uint32_t*)&c01; cv.y = *(uint32_t*)&c23;
    lv.x = *(uint32_t*)&l01; lv.y = *(uint32_t*)&l23;
    ((uint2*)(g_chat + n * D_EMB))[lane] = cv;
    ((uint2*)(g_lhat + n * D_EMB))[lane] = lv;
}

// ---------------------------------------------------------------------------
// Kernel 2: persistent fp16-accum mma.sync GEMM over 148 CTAs.
// Structure identical to R15; only the accumulator dtype changed.
// ---------------------------------------------------------------------------
__global__ void __launch_bounds__(GTHREADS, 1) gemm_lse_kernel(
    const float* __restrict__ wp, const float* __restrict__ bp) {
    extern __shared__ char smem[];
    const uint32_t sb = smem_u32(smem);

    const int tid = threadIdx.x;
    const int wid = tid >> 5, lane = tid & 31;
    const int warp_m = wid >> 2;
    const int warp_n = wid & 3;
    const int gid = lane >> 2;
    const int tid4 = lane & 3;

    const int bid = blockIdx.x;
    const int lo = (bid * TOTAL_TILES) / NCTA;
    const int hi = ((bid + 1) * TOTAL_TILES) / NCTA;

    const float w = *wp, b = *bp;
    const float LOG2E = 1.44269504f;
    const float wl = w * LOG2E, bl = b * LOG2E;

    const float4* A4 = (const float4*)g_lhat;
    const float4* B4 = (const float4*)g_chat;

    // ---- initial loads ----
    int rb = lo >> 5;
    {
        const int ct = lo & 31;
#pragma unroll
        for (int p = 0; p < 8; p++) {
            int idx = p * GTHREADS + tid;
            int r = idx >> 4, c = idx & 15;
            cp16(sb + (uint32_t)(r * ROW_BYTES + ((c ^ (r & 7)) << 4)),
                 &A4[(rb * TM + r) * 16 + c]);
        }
#pragma unroll
        for (int p = 0; p < 16; p++) {
            int idx = p * GTHREADS + tid;
            int r = idx >> 4, c = idx & 15;
            cp16(sb + OFF_B0 + (uint32_t)(r * ROW_BYTES + ((c ^ (r & 7)) << 4)),
                 &B4[(ct * TN + r) * 16 + c]);
        }
        CP_COMMIT();
        CP_WAIT0();
        __syncthreads();
    }

    // ---- ldmatrix lane-relative offsets ----
    uint32_t aOff[4], aSw[4];
    const int aK = lane >> 4;
#pragma unroll
    for (int i = 0; i < 4; i++) {
        int row = warp_m * 64 + i * 16 + (lane & 15);
        aOff[i] = (uint32_t)(row * ROW_BYTES);
        aSw[i] = (uint32_t)(row & 7);
    }
    uint32_t bOff[4], bSw[4];
    const int bK = (lane >> 3) & 1;
    const int nLoc = ((lane >> 4) << 3) + (lane & 7);
#pragma unroll
    for (int j2 = 0; j2 < 4; j2++) {
        int row = warp_n * 64 + j2 * 16 + nLoc;
        bOff[j2] = (uint32_t)(row * ROW_BYTES);
        bSw[j2] = (uint32_t)(row & 7);
    }

    uint32_t acc[4][8][2];               // f16x2 accumulators
    float rs[8];
#pragma unroll
    for (int q = 0; q < 8; q++) rs[q] = 0.f;
    float* red = (float*)(smem + OFF_RED);
    int aCur = 0;
    int segCt = lo & 31;

    for (int t = lo; t < hi; t++) {
        const int bCur = (t - lo) & 1;
        const int ct = t & 31;
        const int rowBase = rb * TM;
        const uint32_t aBuf = sb + (uint32_t)(aCur * A_BYTES);
        const uint32_t bBuf = sb + OFF_B0 + (uint32_t)(bCur * B_BYTES);

        // ---- prefetch next tile ----
        bool aSwap = false;
        if (t + 1 < hi) {
            const int rbn = (t + 1) >> 5, ctn = (t + 1) & 31;
            aSwap = (rbn != rb);
            if (aSwap) {
                const uint32_t nA = sb + (uint32_t)((aCur ^ 1) * A_BYTES);
#pragma unroll
                for (int p = 0; p < 8; p++) {
                    int idx = p * GTHREADS + tid;
                    int r = idx >> 4, c = idx & 15;
                    cp16(nA + (uint32_t)(r * ROW_BYTES + ((c ^ (r & 7)) << 4)),
                         &A4[(rbn * TM + r) * 16 + c]);
                }
            }
            const uint32_t nB = sb + OFF_B0 + (uint32_t)((bCur ^ 1) * B_BYTES);
#pragma unroll
            for (int p = 0; p < 16; p++) {
                int idx = p * GTHREADS + tid;
                int r = idx >> 4, c = idx & 15;
                cp16(nB + (uint32_t)(r * ROW_BYTES + ((c ^ (r & 7)) << 4)),
                     &B4[(ctn * TN + r) * 16 + c]);
            }
            CP_COMMIT();
        }

#pragma unroll
        for (int i = 0; i < 4; i++)
#pragma unroll
            for (int j = 0; j < 8; j++) { acc[i][j][0] = 0u; acc[i][j][1] = 0u; }

        // ---- k-loop: 8 steps of k=16 ----
#pragma unroll
        for (int ks = 0; ks < 8; ks++) {
            uint32_t a[4][4], bq[4][4];
#pragma unroll
            for (int i = 0; i < 4; i++) {
                uint32_t addr = aBuf + aOff[i] + ((((uint32_t)(2 * ks + aK)) ^ aSw[i]) << 4);
                LDMX4(a[i][0], a[i][1], a[i][2], a[i][3], addr);
            }
#pragma unroll
            for (int j2 = 0; j2 < 4; j2++) {
                uint32_t addr = bBuf + bOff[j2] + ((((uint32_t)(2 * ks + bK)) ^ bSw[j2]) << 4);
                LDMX4(bq[j2][0], bq[j2][1], bq[j2][2], bq[j2][3], addr);
            }
#pragma unroll
            for (int i = 0; i < 4; i++)
#pragma unroll
                for (int j = 0; j < 8; j++)
                    mma_f16acc(acc[i][j][0], acc[i][j][1],
                               a[i][0], a[i][1], a[i][2], a[i][3],
                               bq[j >> 1][(j & 1) * 2], bq[j >> 1][(j & 1) * 2 + 1]);
        }

        // ---- epilogue: unpack f16 acc -> exp into segment-persistent rs ----
        const bool isDiag = (ct == (rb >> 1));
        const int dOff = (rb & 1) * 128;
#pragma unroll
        for (int i = 0; i < 4; i++) {
            const int r0 = warp_m * 64 + i * 16 + gid;
#pragma unroll
            for (int j = 0; j < 8; j++) {
                const int c0 = warp_n * 64 + j * 8 + tid4 * 2;
                float2 vlo = __half22float2(*reinterpret_cast<__half2*>(&acc[i][j][0]));
                float2 vhi = __half22float2(*reinterpret_cast<__half2*>(&acc[i][j][1]));
                float e0 = fmaxf(vlo.x, CLAMP_MIN);
                float e1 = fmaxf(vlo.y, CLAMP_MIN);
                float e2 = fmaxf(vhi.x, CLAMP_MIN);
                float e3 = fmaxf(vhi.y, CLAMP_MIN);
                rs[i * 2 + 0] += ex2f(fmaf(e0, wl, bl)) + ex2f(fmaf(e1, wl, bl));
                rs[i * 2 + 1] += ex2f(fmaf(e2, wl, bl)) + ex2f(fmaf(e3, wl, bl));
                if (isDiag) {
                    const int c = c0 - dOff;
                    if (r0 == c)         g_diag[rowBase + r0] = fmaf(e0, w, b);
                    if (r0 == c + 1)     g_diag[rowBase + r0] = fmaf(e1, w, b);
                    if (r0 + 8 == c)     g_diag[rowBase + r0 + 8] = fmaf(e2, w, b);
                    if (r0 + 8 == c + 1) g_diag[rowBase + r0 + 8] = fmaf(e3, w, b);
                }
            }
        }

        // ---- segment flush ----
        const bool last = (t + 1 == hi);
        if (last || aSwap) {
#pragma unroll
            for (int q = 0; q < 8; q++) {
                rs[q] += __shfl_xor_sync(0xffffffffu, rs[q], 1);
                rs[q] += __shfl_xor_sync(0xffffffffu, rs[q], 2);
            }
            if (tid4 == 0) {
#pragma unroll
                for (int i = 0; i < 4; i++) {
                    int r = warp_m * 64 + i * 16 + gid;
                    red[warp_n * 128 + r] = rs[i * 2 + 0];
                    red[warp_n * 128 + r + 8] = rs[i * 2 + 1];
                }
            }
            __syncthreads();
            if (tid < 128)
                g_partF[segCt][rowBase + tid] =
                    red[tid] + red[128 + tid] + red[256 + tid] + red[384 + tid];
#pragma unroll
            for (int q = 0; q < 8; q++) rs[q] = 0.f;
            segCt = 0;
        }

        if (t + 1 < hi) {
            CP_WAIT0();
            __syncthreads();
        }
        if (aSwap) { rb = (t + 1) >> 5; aCur ^= 1; }
    }
}

// ---------------------------------------------------------------------------
// Kernel 3: per-row log(sum) - diag, block-reduced; last CTA sums g_blk.
// ---------------------------------------------------------------------------
__global__ void __launch_bounds__(128) final_kernel(float* __restrict__ out) {
    const int tid = threadIdx.x;
    const int r = blockIdx.x * 128 + tid;
    const float LN2 = 0.69314718056f;
    float sum = 0.f;
#pragma unroll
    for (int ct = 0; ct < NCT; ct++) sum += g_partF[ct][r];
    float s = lg2f(sum) * LN2 - g_diag[r];
#pragma unroll
    for (int o = 16; o; o >>= 1) s += __shfl_xor_sync(0xffffffffu, s, o);
    __shared__ float sred[4];
    __shared__ int sLast;
    if ((tid & 31) == 0) sred[tid >> 5] = s;
    __syncthreads();
    if (tid == 0) {
        g_blk[blockIdx.x] = sred[0] + sred[1] + sred[2] + sred[3];
        __threadfence();
        sLast = (atomicAdd(&g_cnt, 1u) == NRB - 1);
    }
    __syncthreads();
    if (sLast && tid < 32) {
        __threadfence();
        float v = g_blk[tid] + g_blk[tid + 32];
#pragma unroll
        for (int o = 16; o; o >>= 1) v += __shfl_xor_sync(0xffffffffu, v, o);
        if (tid == 0) out[0] = v * (1.0f / (float)N_SPK);
    }
}

extern "C" void kernel_launch(void* const* d_in, const int* in_sizes, int n_in,
                              void* d_out, int out_size) {
    const float* x = (const float*)d_in[0];
    const float* w = (const float*)d_in[1];
    const float* b = (const float*)d_in[2];
    float* out = (float*)d_out;
    (void)in_sizes; (void)n_in; (void)out_size;

    cudaFuncSetAttribute(gemm_lse_kernel,
                         cudaFuncAttributeMaxDynamicSharedMemorySize, SMEM_TOTAL);

    prep_kernel<<<N_SPK / 8, 256>>>(x);
    gemm_lse_kernel<<<NCTA, GTHREADS, SMEM_TOTAL>>>(w, b);
    final_kernel<<<NRB, 128>>>(out);
}

// round 17
// speedup vs baseline: 1.0348x; 1.0348x over previous
#include <cuda_runtime.h>
#include <cuda_bf16.h>
#include <cstdint>

// ---------------- problem constants ----------------
#define N_SPK 8192
#define M_UTT 10
#define D_EMB 128
#define CLAMP_MIN 1e-6f

// ---------------- gemm tiling ----------------
#define TM 128
#define TN 256
#define NCT 32                         // col tiles per row block
#define NRB 64                         // row blocks
#define TOTAL_TILES (NRB * NCT)        // 2048
#define NCTA 148                       // one CTA per SM, one wave
#define GTHREADS 256                   // 8 warps: 2(M) x 4(N), warp tile 64x64

#define ROW_BYTES 256                  // 128 bf16
#define A_BYTES (128 * ROW_BYTES)      // 32 KB
#define B_BYTES (256 * ROW_BYTES)      // 64 KB
#define OFF_B0  (2 * A_BYTES)          // A double buffer at 0 / 32KB
#define OFF_RED (2 * A_BYTES + 2 * B_BYTES)
#define SMEM_TOTAL (OFF_RED + 2048)    // 194 KB + 2KB reduction pad

// ---------------- device scratch ----------------
__device__ __align__(16) __nv_bfloat16 g_lhat[N_SPK * D_EMB];
__device__ __align__(16) __nv_bfloat16 g_chat[N_SPK * D_EMB];
// Sparse per-segment exp-sum partials (slot = segment-start ct); unwritten
// slots stay zero, each written slot has exactly one writer per launch.
__device__ float g_partF[NCT][N_SPK];
__device__ float g_diag[N_SPK];
__device__ float g_blk[NRB];
__device__ unsigned int g_cnt;

// ---------------- helpers ----------------
__device__ __forceinline__ uint32_t smem_u32(const void* p) {
    uint32_t a;
    asm("{ .reg .u64 t; cvta.to.shared.u64 t, %1; cvt.u32.u64 %0, t; }" : "=r"(a) : "l"(p));
    return a;
}
__device__ __forceinline__ void cp16(uint32_t dst, const void* src) {
    asm volatile("cp.async.cg.shared.global [%0], [%1], 16;" :: "r"(dst), "l"(src) : "memory");
}
#define CP_COMMIT() asm volatile("cp.async.commit_group;" ::: "memory")
#define CP_WAIT0()  asm volatile("cp.async.wait_group 0;" ::: "memory")

#define LDMX4(r0, r1, r2, r3, addr)                                            \
    asm volatile("ldmatrix.sync.aligned.m8n8.x4.shared.b16 {%0,%1,%2,%3}, [%4];" \
                 : "=r"(r0), "=r"(r1), "=r"(r2), "=r"(r3) : "r"(addr))

__device__ __forceinline__ void mma_bf16(float4& c, uint32_t a0, uint32_t a1,
                                         uint32_t a2, uint32_t a3,
                                         uint32_t b0, uint32_t b1) {
    asm volatile(
        "mma.sync.aligned.m16n8k16.row.col.f32.bf16.bf16.f32 "
        "{%0,%1,%2,%3}, {%4,%5,%6,%7}, {%8,%9}, {%0,%1,%2,%3};"
        : "+f"(c.x), "+f"(c.y), "+f"(c.z), "+f"(c.w)
        : "r"(a0), "r"(a1), "r"(a2), "r"(a3), "r"(b0), "r"(b1));
}

__device__ __forceinline__ float ex2f(float x) {
    float r; asm("ex2.approx.ftz.f32 %0, %1;" : "=f"(r) : "f"(x)); return r;
}
__device__ __forceinline__ float lg2f(float x) {
    float r; asm("lg2.approx.f32 %0, %1;" : "=f"(r) : "f"(x)); return r;
}

// ---------------------------------------------------------------------------
// Kernel 1: centroids + normalization + bf16 rounding.
// 16 lanes per speaker (8 dims each), 2 speakers per warp.
// 20 outstanding LDG.128 per thread; STG.128 stores. Grid 512 x 256.
// ---------------------------------------------------------------------------
__global__ void __launch_bounds__(256) prep_kernel(const float* __restrict__ x) {
    if (blockIdx.x == 0 && threadIdx.x == 0) g_cnt = 0;

    const int tid = threadIdx.x;
    const int lane = tid & 31;
    const int half = lane >> 4;                       // speaker within warp
    const int sl = lane & 15;                         // sub-lane 0..15
    const int n = ((blockIdx.x * 256 + tid) >> 5) * 2 + half;
    const float4* xs = (const float4*)(x + (size_t)n * (M_UTT * D_EMB));

    // thread covers dims sl*8 .. sl*8+7  (float4 indices sl*2, sl*2+1)
    float4 c0 = make_float4(0.f, 0.f, 0.f, 0.f);
    float4 c1 = make_float4(0.f, 0.f, 0.f, 0.f);
    float4 l0, l1;
#pragma unroll
    for (int m = 0; m < M_UTT; m++) {
        float4 v0 = xs[m * 32 + sl * 2];
        float4 v1 = xs[m * 32 + sl * 2 + 1];
        c0.x += v0.x; c0.y += v0.y; c0.z += v0.z; c0.w += v0.w;
        c1.x += v1.x; c1.y += v1.y; c1.z += v1.z; c1.w += v1.w;
        if (m == M_UTT - 1) { l0 = v0; l1 = v1; }
    }
    c0.x *= 0.1f; c0.y *= 0.1f; c0.z *= 0.1f; c0.w *= 0.1f;
    c1.x *= 0.1f; c1.y *= 0.1f; c1.z *= 0.1f; c1.w *= 0.1f;

    float sc = c0.x * c0.x + c0.y * c0.y + c0.z * c0.z + c0.w * c0.w
             + c1.x * c1.x + c1.y * c1.y + c1.z * c1.z + c1.w * c1.w;
    float sl2 = l0.x * l0.x + l0.y * l0.y + l0.z * l0.z + l0.w * l0.w
              + l1.x * l1.x + l1.y * l1.y + l1.z * l1.z + l1.w * l1.w;
    // reduce across the 16 sub-lanes of this speaker (xor stays within half)
#pragma unroll
    for (int o = 8; o; o >>= 1) {
        sc += __shfl_xor_sync(0xffffffffu, sc, o);
        sl2 += __shfl_xor_sync(0xffffffffu, sl2, o);
    }
    const float rc = rsqrtf(sc), rl = rsqrtf(sl2);

    __nv_bfloat162 ca = __floats2bfloat162_rn(c0.x * rc, c0.y * rc);
    __nv_bfloat162 cb = __floats2bfloat162_rn(c0.z * rc, c0.w * rc);
    __nv_bfloat162 cc = __floats2bfloat162_rn(c1.x * rc, c1.y * rc);
    __nv_bfloat162 cd = __floats2bfloat162_rn(c1.z * rc, c1.w * rc);
    __nv_bfloat162 la = __floats2bfloat162_rn(l0.x * rl, l0.y * rl);
    __nv_bfloat162 lb = __floats2bfloat162_rn(l0.z * rl, l0.w * rl);
    __nv_bfloat162 lc = __floats2bfloat162_rn(l1.x * rl, l1.y * rl);
    __nv_bfloat162 ld = __floats2bfloat162_rn(l1.z * rl, l1.w * rl);

    uint4 cv, lv;
    cv.x = *(uint32_t*)&ca; cv.y = *(uint32_t*)&cb;
    cv.z = *(uint32_t*)&cc; cv.w = *(uint32_t*)&cd;
    lv.x = *(uint32_t*)&la; lv.y = *(uint32_t*)&lb;
    lv.z = *(uint32_t*)&lc; lv.w = *(uint32_t*)&ld;
    ((uint4*)(g_chat + n * D_EMB))[sl] = cv;
    ((uint4*)(g_lhat + n * D_EMB))[sl] = lv;
}

// ---------------------------------------------------------------------------
// Kernel 2: persistent bf16 mma.sync GEMM over 148 CTAs (R15 structure).
// 2048 tiles (64 rb x 32 ct); CTA k owns [k*2048/148,(k+1)*2048/148).
// Row exp-sums accumulate in registers per segment; one flush per segment.
// ---------------------------------------------------------------------------
__global__ void __launch_bounds__(GTHREADS, 1) gemm_lse_kernel(
    const float* __restrict__ wp, const float* __restrict__ bp) {
    extern __shared__ char smem[];
    const uint32_t sb = smem_u32(smem);

    const int tid = threadIdx.x;
    const int wid = tid >> 5, lane = tid & 31;
    const int warp_m = wid >> 2;
    const int warp_n = wid & 3;
    const int gid = lane >> 2;
    const int tid4 = lane & 3;

    const int bid = blockIdx.x;
    const int lo = (bid * TOTAL_TILES) / NCTA;
    const int hi = ((bid + 1) * TOTAL_TILES) / NCTA;

    const float w = *wp, b = *bp;
    const float LOG2E = 1.44269504f;
    const float wl = w * LOG2E, bl = b * LOG2E;

    const float4* A4 = (const float4*)g_lhat;
    const float4* B4 = (const float4*)g_chat;

    // ---- initial loads ----
    int rb = lo >> 5;
    {
        const int ct = lo & 31;
#pragma unroll
        for (int p = 0; p < 8; p++) {
            int idx = p * GTHREADS + tid;
            int r = idx >> 4, c = idx & 15;
            cp16(sb + (uint32_t)(r * ROW_BYTES + ((c ^ (r & 7)) << 4)),
                 &A4[(rb * TM + r) * 16 + c]);
        }
#pragma unroll
        for (int p = 0; p < 16; p++) {
            int idx = p * GTHREADS + tid;
            int r = idx >> 4, c = idx & 15;
            cp16(sb + OFF_B0 + (uint32_t)(r * ROW_BYTES + ((c ^ (r & 7)) << 4)),
                 &B4[(ct * TN + r) * 16 + c]);
        }
        CP_COMMIT();
        CP_WAIT0();
        __syncthreads();
    }

    // ---- ldmatrix lane-relative offsets ----
    uint32_t aOff[4], aSw[4];
    const int aK = lane >> 4;
#pragma unroll
    for (int i = 0; i < 4; i++) {
        int row = warp_m * 64 + i * 16 + (lane & 15);
        aOff[i] = (uint32_t)(row * ROW_BYTES);
        aSw[i] = (uint32_t)(row & 7);
    }
    uint32_t bOff[4], bSw[4];
    const int bK = (lane >> 3) & 1;
    const int nLoc = ((lane >> 4) << 3) + (lane & 7);
#pragma unroll
    for (int j2 = 0; j2 < 4; j2++) {
        int row = warp_n * 64 + j2 * 16 + nLoc;
        bOff[j2] = (uint32_t)(row * ROW_BYTES);
        bSw[j2] = (uint32_t)(row & 7);
    }

    float4 acc[4][8];
    float rs[8];
#pragma unroll
    for (int q = 0; q < 8; q++) rs[q] = 0.f;
    float* red = (float*)(smem + OFF_RED);
    int aCur = 0;
    int segCt = lo & 31;

    for (int t = lo; t < hi; t++) {
        const int bCur = (t - lo) & 1;
        const int ct = t & 31;
        const int rowBase = rb * TM;
        const uint32_t aBuf = sb + (uint32_t)(aCur * A_BYTES);
        const uint32_t bBuf = sb + OFF_B0 + (uint32_t)(bCur * B_BYTES);

        // ---- prefetch next tile (B always; A only on row-block change) ----
        bool aSwap = false;
        if (t + 1 < hi) {
            const int rbn = (t + 1) >> 5, ctn = (t + 1) & 31;
            aSwap = (rbn != rb);
            if (aSwap) {
                const uint32_t nA = sb + (uint32_t)((aCur ^ 1) * A_BYTES);
#pragma unroll
                for (int p = 0; p < 8; p++) {
                    int idx = p * GTHREADS + tid;
                    int r = idx >> 4, c = idx & 15;
                    cp16(nA + (uint32_t)(r * ROW_BYTES + ((c ^ (r & 7)) << 4)),
                         &A4[(rbn * TM + r) * 16 + c]);
                }
            }
            const uint32_t nB = sb + OFF_B0 + (uint32_t)((bCur ^ 1) * B_BYTES);
#pragma unroll
            for (int p = 0; p < 16; p++) {
                int idx = p * GTHREADS + tid;
                int r = idx >> 4, c = idx & 15;
                cp16(nB + (uint32_t)(r * ROW_BYTES + ((c ^ (r & 7)) << 4)),
                     &B4[(ctn * TN + r) * 16 + c]);
            }
            CP_COMMIT();
        }

#pragma unroll
        for (int i = 0; i < 4; i++)
#pragma unroll
            for (int j = 0; j < 8; j++) acc[i][j] = make_float4(0.f, 0.f, 0.f, 0.f);

        // ---- k-loop: 8 steps of k=16 ----
#pragma unroll
        for (int ks = 0; ks < 8; ks++) {
            uint32_t a[4][4], bq[4][4];
#pragma unroll
            for (int i = 0; i < 4; i++) {
                uint32_t addr = aBuf + aOff[i] + ((((uint32_t)(2 * ks + aK)) ^ aSw[i]) << 4);
                LDMX4(a[i][0], a[i][1], a[i][2], a[i][3], addr);
            }
#pragma unroll
            for (int j2 = 0; j2 < 4; j2++) {
                uint32_t addr = bBuf + bOff[j2] + ((((uint32_t)(2 * ks + bK)) ^ bSw[j2]) << 4);
                LDMX4(bq[j2][0], bq[j2][1], bq[j2][2], bq[j2][3], addr);
            }
#pragma unroll
            for (int i = 0; i < 4; i++)
#pragma unroll
                for (int j = 0; j < 8; j++)
                    mma_bf16(acc[i][j], a[i][0], a[i][1], a[i][2], a[i][3],
                             bq[j >> 1][(j & 1) * 2], bq[j >> 1][(j & 1) * 2 + 1]);
        }

        // ---- epilogue: exp from registers into segment-persistent rs ----
        const bool isDiag = (ct == (rb >> 1));
        const int dOff = (rb & 1) * 128;
#pragma unroll
        for (int i = 0; i < 4; i++) {
            const int r0 = warp_m * 64 + i * 16 + gid;
#pragma unroll
            for (int j = 0; j < 8; j++) {
                const int c0 = warp_n * 64 + j * 8 + tid4 * 2;
                float4 v = acc[i][j];
                float e0 = fmaxf(v.x, CLAMP_MIN);
                float e1 = fmaxf(v.y, CLAMP_MIN);
                float e2 = fmaxf(v.z, CLAMP_MIN);
                float e3 = fmaxf(v.w, CLAMP_MIN);
                rs[i * 2 + 0] += ex2f(fmaf(e0, wl, bl)) + ex2f(fmaf(e1, wl, bl));
                rs[i * 2 + 1] += ex2f(fmaf(e2, wl, bl)) + ex2f(fmaf(e3, wl, bl));
                if (isDiag) {
                    const int c = c0 - dOff;
                    if (r0 == c)         g_diag[rowBase + r0] = fmaf(e0, w, b);
                    if (r0 == c + 1)     g_diag[rowBase + r0] = fmaf(e1, w, b);
                    if (r0 + 8 == c)     g_diag[rowBase + r0 + 8] = fmaf(e2, w, b);
                    if (r0 + 8 == c + 1) g_diag[rowBase + r0 + 8] = fmaf(e3, w, b);
                }
            }
        }

        // ---- segment flush: only on row-block change or final tile ----
        const bool last = (t + 1 == hi);
        if (last || aSwap) {
#pragma unroll
            for (int q = 0; q < 8; q++) {
                rs[q] += __shfl_xor_sync(0xffffffffu, rs[q], 1);
                rs[q] += __shfl_xor_sync(0xffffffffu, rs[q], 2);
            }
            if (tid4 == 0) {
#pragma unroll
                for (int i = 0; i < 4; i++) {
                    int r = warp_m * 64 + i * 16 + gid;
                    red[warp_n * 128 + r] = rs[i * 2 + 0];
                    red[warp_n * 128 + r + 8] = rs[i * 2 + 1];
                }
            }
            __syncthreads();
            if (tid < 128)
                g_partF[segCt][rowBase + tid] =
                    red[tid] + red[128 + tid] + red[256 + tid] + red[384 + tid];
#pragma unroll
            for (int q = 0; q < 8; q++) rs[q] = 0.f;
            segCt = 0;
        }

        if (t + 1 < hi) {
            CP_WAIT0();
            __syncthreads();
        }
        if (aSwap) { rb = (t + 1) >> 5; aCur ^= 1; }
    }
}

// ---------------------------------------------------------------------------
// Kernel 3: per-row log(sum) - diag, block-reduced; last CTA sums g_blk.
// ---------------------------------------------------------------------------
__global__ void __launch_bounds__(128) final_kernel(float* __restrict__ out) {
    const int tid = threadIdx.x;
    const int r = blockIdx.x * 128 + tid;
    const float LN2 = 0.69314718056f;
    float sum = 0.f;
#pragma unroll
    for (int ct = 0; ct < NCT; ct++) sum += g_partF[ct][r];
    float s = lg2f(sum) * LN2 - g_diag[r];
#pragma unroll
    for (int o = 16; o; o >>= 1) s += __shfl_xor_sync(0xffffffffu, s, o);
    __shared__ float sred[4];
    __shared__ int sLast;
    if ((tid & 31) == 0) sred[tid >> 5] = s;
    __syncthreads();
    if (tid == 0) {
        g_blk[blockIdx.x] = sred[0] + sred[1] + sred[2] + sred[3];
        __threadfence();
        sLast = (atomicAdd(&g_cnt, 1u) == NRB - 1);
    }
    __syncthreads();
    if (sLast && tid < 32) {
        __threadfence();
        float v = g_blk[tid] + g_blk[tid + 32];
#pragma unroll
        for (int o = 16; o; o >>= 1) v += __shfl_xor_sync(0xffffffffu, v, o);
        if (tid == 0) out[0] = v * (1.0f / (float)N_SPK);
    }
}

extern "C" void kernel_launch(void* const* d_in, const int* in_sizes, int n_in,
                              void* d_out, int out_size) {
    const float* x = (const float*)d_in[0];
    const float* w = (const float*)d_in[1];
    const float* b = (const float*)d_in[2];
    float* out = (float*)d_out;
    (void)in_sizes; (void)n_in; (void)out_size;

    cudaFuncSetAttribute(gemm_lse_kernel,
                         cudaFuncAttributeMaxDynamicSharedMemorySize, SMEM_TOTAL);

    prep_kernel<<<512, 256>>>(x);
    gemm_lse_kernel<<<NCTA, GTHREADS, SMEM_TOTAL>>>(w, b);
    final_kernel<<<NRB, 128>>>(out);
}